// round 5
// baseline (speedup 1.0000x reference)
#include <cuda_runtime.h>
#include <math.h>

#define BATCH 2
#define HH 512
#define WW 512
#define NC 21
#define PH 128
#define PW 128
#define KS 11
#define K2 121
#define PPLANE (PH*PW)

// -------- scratch (device globals; no allocation allowed) --------
__device__ float g_unary[BATCH*NC*HH*WW];   // 44 MB
__device__ float g_rgbp [BATCH*3*PPLANE];
__device__ float g_wkern[BATCH*K2*PPLANE];  // 15.9 MB (pw0*k_bilateral + pw1*k_spatial)
__device__ float g_Qb   [BATCH*NC*PPLANE];
__device__ float g_msg  [BATCH*NC*PPLANE];

// -------- 3x3 conv backbone: x[B,3,H,W] -> unary[B,21,H,W] --------
__global__ __launch_bounds__(256) void k_unary(const float* __restrict__ x,
                                               const float* __restrict__ w,
                                               const float* __restrict__ bias)
{
    __shared__ float sw[NC*27];
    __shared__ float sb[NC];
    for (int i = threadIdx.x; i < NC*27; i += 256) sw[i] = w[i];
    if (threadIdx.x < NC) sb[threadIdx.x] = bias[threadIdx.x];
    __syncthreads();

    int idx = blockIdx.x*256 + threadIdx.x;
    if (idx >= BATCH*HH*WW) return;
    int xc = idx % WW;
    int y  = (idx / WW) % HH;
    int b  = idx / (WW*HH);

    float v[27];
#pragma unroll
    for (int ci = 0; ci < 3; ci++)
#pragma unroll
        for (int ky = 0; ky < 3; ky++)
#pragma unroll
            for (int kx = 0; kx < 3; kx++) {
                int yy = y + ky - 1, xx = xc + kx - 1;
                float t = 0.f;
                if (yy >= 0 && yy < HH && xx >= 0 && xx < WW)
                    t = __ldg(&x[((b*3 + ci)*HH + yy)*WW + xx]);
                v[(ci*3 + ky)*3 + kx] = t;
            }
#pragma unroll
    for (int o = 0; o < NC; o++) {
        float a = sb[o];
#pragma unroll
        for (int j = 0; j < 27; j++) a += v[j] * sw[o*27 + j];
        g_unary[((b*NC + o)*HH + y)*WW + xc] = a;
    }
}

// -------- pooled rgb features: avgpool4(x)/13 --------
__global__ __launch_bounds__(256) void k_poolrgb(const float* __restrict__ x)
{
    int idx = blockIdx.x*256 + threadIdx.x;
    if (idx >= BATCH*3*PPLANE) return;
    int pw_ = idx % PW;
    int ph_ = (idx / PW) % PH;
    int c   = (idx / PPLANE) % 3;
    int b   = idx / (PPLANE*3);
    const float* p = &x[((b*3 + c)*HH + ph_*4)*WW + pw_*4];
    float s = 0.f;
#pragma unroll
    for (int i = 0; i < 4; i++)
#pragma unroll
        for (int j = 0; j < 4; j++) s += __ldg(&p[i*WW + j]);
    g_rgbp[idx] = s * (1.f/16.f) * (1.f/13.f);
}

// -------- combined pairwise kernel: wkern = pw0*exp(-.5||d_bi||^2)+pw1*exp(-.5||d_sp||^2) --------
__global__ __launch_bounds__(128) void k_wkern(const float* __restrict__ pwts)
{
    int idx = blockIdx.x*128 + threadIdx.x;
    if (idx >= BATCH*PPLANE) return;
    int pw_ = idx % PW;
    int ph_ = (idx / PW) % PH;
    int b   = idx / PPLANE;
    float p0 = __ldg(&pwts[0]), p1 = __ldg(&pwts[1]);

    float cy = 4.f*ph_ + 1.5f;   // pooled y coordinate (avg of 4 ints)
    float cx = 4.f*pw_ + 1.5f;
    float cb0 = cy*(1.f/80.f), cb1 = cx*(1.f/80.f);
    float cs0 = cy*(1.f/3.f),  cs1 = cx*(1.f/3.f);

    const float* rp = &g_rgbp[(b*3)*PPLANE];
    float cr = rp[ph_*PW + pw_];
    float cg = rp[PPLANE + ph_*PW + pw_];
    float cB = rp[2*PPLANE + ph_*PW + pw_];

    float* wout = &g_wkern[(b*K2)*PPLANE + ph_*PW + pw_];
    for (int ky = 0; ky < KS; ky++) {
        int ny = ph_ + ky - 5;
        for (int kx = 0; kx < KS; kx++) {
            int nx = pw_ + kx - 5;
            float db0, db1, db2, db3, db4, ds0, ds1;
            if (ny >= 0 && ny < PH && nx >= 0 && nx < PW) {
                float nyf = 4.f*ny + 1.5f, nxf = 4.f*nx + 1.5f;
                db0 = (nyf - cy)*(1.f/80.f);
                db1 = (nxf - cx)*(1.f/80.f);
                db2 = __ldg(&rp[ny*PW + nx]) - cr;
                db3 = __ldg(&rp[PPLANE + ny*PW + nx]) - cg;
                db4 = __ldg(&rp[2*PPLANE + ny*PW + nx]) - cB;
                ds0 = (nyf - cy)*(1.f/3.f);
                ds1 = (nxf - cx)*(1.f/3.f);
            } else {               // zero-padded patches: d = 0 - f_center
                db0 = -cb0; db1 = -cb1; db2 = -cr; db3 = -cg; db4 = -cB;
                ds0 = -cs0; ds1 = -cs1;
            }
            float kb = expf(-0.5f*(db0*db0 + db1*db1 + db2*db2 + db3*db3 + db4*db4));
            float ks = expf(-0.5f*(ds0*ds0 + ds1*ds1));
            wout[(ky*KS + kx)*PPLANE] = p0*kb + p1*ks;
        }
    }
}

// -------- fused: logQ = (use_msg ? uw*unary + up4(msg) : unary); Qb = pool4(softmax(logQ)) --------
// block = 128 threads = 128 input cols (32 pooled cols), one pooled row; grid (4, 128, B)
__global__ __launch_bounds__(128) void k_softpool(const float* __restrict__ uw_p, int use_msg)
{
    int b    = blockIdx.z;
    int pr   = blockIdx.y;                 // pooled row
    int tile = blockIdx.x;                 // pooled-col tile (32 wide)
    int tid  = threadIdx.x;
    int xc   = tile*128 + tid;             // input col
    float uw = __ldg(uw_p);

    // x bilinear indices (constant across rows for this thread)
    float srcX = (xc + 0.5f)*0.25f - 0.5f;
    srcX = fminf(fmaxf(srcX, 0.f), 127.f);
    int   x0 = (int)floorf(srcX);
    int   x1 = min(x0 + 1, 127);
    float wx = srcX - (float)x0;

    float acc[NC];
#pragma unroll
    for (int c = 0; c < NC; c++) acc[c] = 0.f;

    for (int iy = 0; iy < 4; iy++) {
        int y = pr*4 + iy;
        float l[NC];
        if (!use_msg) {
#pragma unroll
            for (int c = 0; c < NC; c++)
                l[c] = __ldg(&g_unary[((b*NC + c)*HH + y)*WW + xc]);
        } else {
            float srcY = (y + 0.5f)*0.25f - 0.5f;
            srcY = fminf(fmaxf(srcY, 0.f), 127.f);
            int   y0 = (int)floorf(srcY);
            int   y1 = min(y0 + 1, 127);
            float wy = srcY - (float)y0;
            float w00 = (1.f - wy)*(1.f - wx), w01 = (1.f - wy)*wx;
            float w10 = wy*(1.f - wx),         w11 = wy*wx;
#pragma unroll
            for (int c = 0; c < NC; c++) {
                const float* mp = &g_msg[(b*NC + c)*PPLANE];
                float m = w00*__ldg(&mp[y0*PW + x0]) + w01*__ldg(&mp[y0*PW + x1])
                        + w10*__ldg(&mp[y1*PW + x0]) + w11*__ldg(&mp[y1*PW + x1]);
                l[c] = uw*__ldg(&g_unary[((b*NC + c)*HH + y)*WW + xc]) + m;
            }
        }
        float mx = l[0];
#pragma unroll
        for (int c = 1; c < NC; c++) mx = fmaxf(mx, l[c]);
        float s = 0.f;
#pragma unroll
        for (int c = 0; c < NC; c++) { l[c] = __expf(l[c] - mx); s += l[c]; }
        float inv = 1.f / s;
#pragma unroll
        for (int c = 0; c < NC; c++) acc[c] += l[c]*inv;
    }
    // sum over groups of 4 lanes (4 input cols -> 1 pooled col)
#pragma unroll
    for (int c = 0; c < NC; c++) {
        float v = acc[c];
        v += __shfl_down_sync(0xffffffffu, v, 1);
        v += __shfl_down_sync(0xffffffffu, v, 2);
        acc[c] = v;
    }
    if ((tid & 3) == 0) {
        int pc = tile*32 + (tid >> 2);
#pragma unroll
        for (int c = 0; c < NC; c++)
            g_Qb[((b*NC + c)*PH + pr)*PW + pc] = acc[c]*(1.f/16.f);
    }
}

// -------- PAC message: msg[b,c,p] = sum_k wkern[b,k,p] * Qb[b,c,p+off(k)] (zero pad) --------
// block = 128 threads = pooled tile 32x4; channels processed 7 at a time via smem tiles
#define CHB 7
__global__ __launch_bounds__(128) void k_pac()
{
    __shared__ float sQ[CHB][14][42];      // rows: tile 4 + halo 10; cols: 32 + 10
    int b   = blockIdx.z;
    int ty0 = blockIdx.y * 4;              // pooled row origin
    int tx0 = blockIdx.x * 32;             // pooled col origin
    int tid = threadIdx.x;
    int tx  = tid & 31, ty = tid >> 5;
    int ph_ = ty0 + ty, pw_ = tx0 + tx;

    const float* wptr = &g_wkern[(b*K2)*PPLANE + ph_*PW + pw_];

    for (int cb = 0; cb < NC; cb += CHB) {
        __syncthreads();                   // protect smem reuse across passes
        for (int i = tid; i < CHB*14*42; i += 128) {
            int c   = i / (14*42);
            int r   = (i / 42) % 14;
            int col = i % 42;
            int gy = ty0 + r - 5, gx = tx0 + col - 5;
            float v = 0.f;
            if (gy >= 0 && gy < PH && gx >= 0 && gx < PW)
                v = __ldg(&g_Qb[((b*NC + cb + c)*PH + gy)*PW + gx]);
            sQ[c][r][col] = v;
        }
        __syncthreads();

        float acc[CHB];
#pragma unroll
        for (int c = 0; c < CHB; c++) acc[c] = 0.f;

        for (int ky = 0; ky < KS; ky++) {
#pragma unroll
            for (int kx = 0; kx < KS; kx++) {
                float wv = __ldg(wptr + (ky*KS + kx)*PPLANE);
                const float* s = &sQ[0][ty + ky][tx + kx];
#pragma unroll
                for (int c = 0; c < CHB; c++)
                    acc[c] += wv * s[c*(14*42)];
            }
        }
#pragma unroll
        for (int c = 0; c < CHB; c++)
            g_msg[((b*NC + cb + c)*PH + ph_)*PW + pw_] = acc[c];
    }
}

// -------- final: out = uw*unary + up4(msg), written to d_out --------
__global__ __launch_bounds__(256) void k_final(const float* __restrict__ uw_p,
                                               float* __restrict__ out)
{
    int i = blockIdx.x*256 + threadIdx.x;
    if (i >= BATCH*NC*HH*WW) return;
    int x  = i & (WW - 1);
    int y  = (i >> 9) & (HH - 1);
    int bc = i >> 18;                      // b*21 + c
    float uw = __ldg(uw_p);

    float srcY = (y + 0.5f)*0.25f - 0.5f;
    srcY = fminf(fmaxf(srcY, 0.f), 127.f);
    int   y0 = (int)floorf(srcY);
    int   y1 = min(y0 + 1, 127);
    float wy = srcY - (float)y0;

    float srcX = (x + 0.5f)*0.25f - 0.5f;
    srcX = fminf(fmaxf(srcX, 0.f), 127.f);
    int   x0 = (int)floorf(srcX);
    int   x1 = min(x0 + 1, 127);
    float wx = srcX - (float)x0;

    const float* mp = &g_msg[bc*PPLANE];
    float m = (1.f - wy)*((1.f - wx)*__ldg(&mp[y0*PW + x0]) + wx*__ldg(&mp[y0*PW + x1]))
            +        wy *((1.f - wx)*__ldg(&mp[y1*PW + x0]) + wx*__ldg(&mp[y1*PW + x1]));
    out[i] = uw*__ldg(&g_unary[i]) + m;
}

extern "C" void kernel_launch(void* const* d_in, const int* in_sizes, int n_in,
                              void* d_out, int out_size)
{
    const float* x    = (const float*)d_in[0];
    const float* w    = (const float*)d_in[1];
    const float* bias = (const float*)d_in[2];
    const float* uw   = (const float*)d_in[3];
    const float* pwts = (const float*)d_in[4];
    float* out = (float*)d_out;

    (void)in_sizes; (void)n_in; (void)out_size;

    // backbone + edge features + combined pairwise kernel (once)
    k_unary  <<<(BATCH*HH*WW + 255)/256, 256>>>(x, w, bias);
    k_poolrgb<<<(BATCH*3*PPLANE + 255)/256, 256>>>(x);
    k_wkern  <<<(BATCH*PPLANE + 127)/128, 128>>>(pwts);

    dim3 gSoft(4, PH, BATCH);
    dim3 gPac (PW/32, PH/4, BATCH);

    // step 0: Qb = pool(softmax(unary))
    k_softpool<<<gSoft, 128>>>(uw, 0);
    // 5 mean-field steps; intermediate logQ never materialized
    for (int t = 0; t < 5; t++) {
        k_pac<<<gPac, 128>>>();
        if (t < 4) k_softpool<<<gSoft, 128>>>(uw, 1);
        else       k_final<<<(BATCH*NC*HH*WW + 255)/256, 256>>>(uw, out);
    }
}

// round 6
// speedup vs baseline: 1.5037x; 1.5037x over previous
#include <cuda_runtime.h>
#include <math.h>

#define BATCH 2
#define HH 512
#define WW 512
#define NC 21
#define PH 128
#define PW 128
#define KS 11
#define K2 121
#define PPLANE (PH*PW)

// -------- scratch (device globals; no allocation allowed) --------
__device__ float g_unary[BATCH*NC*HH*WW];   // 44 MB
__device__ float g_rgbp [BATCH*3*PPLANE];
__device__ float g_wkern[BATCH*K2*PPLANE];  // 15.9 MB (pw0*k_bilateral + pw1*k_spatial)
__device__ float g_Qb   [BATCH*NC*PPLANE];
__device__ float g_msg  [BATCH*NC*PPLANE];

// -------- 3x3 conv backbone: x[B,3,H,W] -> unary[B,21,H,W] --------
__global__ __launch_bounds__(256) void k_unary(const float* __restrict__ x,
                                               const float* __restrict__ w,
                                               const float* __restrict__ bias)
{
    __shared__ float sw[NC*27];
    __shared__ float sb[NC];
    for (int i = threadIdx.x; i < NC*27; i += 256) sw[i] = w[i];
    if (threadIdx.x < NC) sb[threadIdx.x] = bias[threadIdx.x];
    __syncthreads();

    int idx = blockIdx.x*256 + threadIdx.x;
    if (idx >= BATCH*HH*WW) return;
    int xc = idx % WW;
    int y  = (idx / WW) % HH;
    int b  = idx / (WW*HH);

    float v[27];
#pragma unroll
    for (int ci = 0; ci < 3; ci++)
#pragma unroll
        for (int ky = 0; ky < 3; ky++)
#pragma unroll
            for (int kx = 0; kx < 3; kx++) {
                int yy = y + ky - 1, xx = xc + kx - 1;
                float t = 0.f;
                if (yy >= 0 && yy < HH && xx >= 0 && xx < WW)
                    t = __ldg(&x[((b*3 + ci)*HH + yy)*WW + xx]);
                v[(ci*3 + ky)*3 + kx] = t;
            }
#pragma unroll
    for (int o = 0; o < NC; o++) {
        float a = sb[o];
#pragma unroll
        for (int j = 0; j < 27; j++) a += v[j] * sw[o*27 + j];
        g_unary[((b*NC + o)*HH + y)*WW + xc] = a;
    }
}

// -------- pooled rgb features: avgpool4(x)/13 --------
__global__ __launch_bounds__(256) void k_poolrgb(const float* __restrict__ x)
{
    int idx = blockIdx.x*256 + threadIdx.x;
    if (idx >= BATCH*3*PPLANE) return;
    int pw_ = idx % PW;
    int ph_ = (idx / PW) % PH;
    int c   = (idx / PPLANE) % 3;
    int b   = idx / (PPLANE*3);
    const float* p = &x[((b*3 + c)*HH + ph_*4)*WW + pw_*4];
    float s = 0.f;
#pragma unroll
    for (int i = 0; i < 4; i++)
#pragma unroll
        for (int j = 0; j < 4; j++) s += __ldg(&p[i*WW + j]);
    g_rgbp[idx] = s * (1.f/16.f) * (1.f/13.f);
}

// -------- combined pairwise kernel: wkern = pw0*exp(-.5||d_bi||^2)+pw1*exp(-.5||d_sp||^2) --------
__global__ __launch_bounds__(128) void k_wkern(const float* __restrict__ pwts)
{
    int idx = blockIdx.x*128 + threadIdx.x;
    if (idx >= BATCH*PPLANE) return;
    int pw_ = idx % PW;
    int ph_ = (idx / PW) % PH;
    int b   = idx / PPLANE;
    float p0 = __ldg(&pwts[0]), p1 = __ldg(&pwts[1]);

    float cy = 4.f*ph_ + 1.5f;   // pooled y coordinate (avg of 4 ints)
    float cx = 4.f*pw_ + 1.5f;
    float cb0 = cy*(1.f/80.f), cb1 = cx*(1.f/80.f);
    float cs0 = cy*(1.f/3.f),  cs1 = cx*(1.f/3.f);

    const float* rp = &g_rgbp[(b*3)*PPLANE];
    float cr = rp[ph_*PW + pw_];
    float cg = rp[PPLANE + ph_*PW + pw_];
    float cB = rp[2*PPLANE + ph_*PW + pw_];

    float* wout = &g_wkern[(b*K2)*PPLANE + ph_*PW + pw_];
    for (int ky = 0; ky < KS; ky++) {
        int ny = ph_ + ky - 5;
        for (int kx = 0; kx < KS; kx++) {
            int nx = pw_ + kx - 5;
            float db0, db1, db2, db3, db4, ds0, ds1;
            if (ny >= 0 && ny < PH && nx >= 0 && nx < PW) {
                float nyf = 4.f*ny + 1.5f, nxf = 4.f*nx + 1.5f;
                db0 = (nyf - cy)*(1.f/80.f);
                db1 = (nxf - cx)*(1.f/80.f);
                db2 = __ldg(&rp[ny*PW + nx]) - cr;
                db3 = __ldg(&rp[PPLANE + ny*PW + nx]) - cg;
                db4 = __ldg(&rp[2*PPLANE + ny*PW + nx]) - cB;
                ds0 = (nyf - cy)*(1.f/3.f);
                ds1 = (nxf - cx)*(1.f/3.f);
            } else {               // zero-padded patches: d = 0 - f_center
                db0 = -cb0; db1 = -cb1; db2 = -cr; db3 = -cg; db4 = -cB;
                ds0 = -cs0; ds1 = -cs1;
            }
            float kb = expf(-0.5f*(db0*db0 + db1*db1 + db2*db2 + db3*db3 + db4*db4));
            float ks = expf(-0.5f*(ds0*ds0 + ds1*ds1));
            wout[(ky*KS + kx)*PPLANE] = p0*kb + p1*ks;
        }
    }
}

// -------- fused: logQ = (use_msg ? uw*unary + up4(msg) : unary); Qb = pool4(softmax(logQ)) --------
// block = 128 threads = 128 input cols (32 pooled cols), one pooled row; grid (4, 128, B)
__global__ __launch_bounds__(128) void k_softpool(const float* __restrict__ uw_p, int use_msg)
{
    int b    = blockIdx.z;
    int pr   = blockIdx.y;                 // pooled row
    int tile = blockIdx.x;                 // pooled-col tile (32 wide)
    int tid  = threadIdx.x;
    int xc   = tile*128 + tid;             // input col
    float uw = __ldg(uw_p);

    // x bilinear indices (constant across rows for this thread)
    float srcX = (xc + 0.5f)*0.25f - 0.5f;
    srcX = fminf(fmaxf(srcX, 0.f), 127.f);
    int   x0 = (int)floorf(srcX);
    int   x1 = min(x0 + 1, 127);
    float wx = srcX - (float)x0;

    float acc[NC];
#pragma unroll
    for (int c = 0; c < NC; c++) acc[c] = 0.f;

    for (int iy = 0; iy < 4; iy++) {
        int y = pr*4 + iy;
        float l[NC];
        if (!use_msg) {
#pragma unroll
            for (int c = 0; c < NC; c++)
                l[c] = __ldg(&g_unary[((b*NC + c)*HH + y)*WW + xc]);
        } else {
            float srcY = (y + 0.5f)*0.25f - 0.5f;
            srcY = fminf(fmaxf(srcY, 0.f), 127.f);
            int   y0 = (int)floorf(srcY);
            int   y1 = min(y0 + 1, 127);
            float wy = srcY - (float)y0;
            float w00 = (1.f - wy)*(1.f - wx), w01 = (1.f - wy)*wx;
            float w10 = wy*(1.f - wx),         w11 = wy*wx;
#pragma unroll
            for (int c = 0; c < NC; c++) {
                const float* mp = &g_msg[(b*NC + c)*PPLANE];
                float m = w00*__ldg(&mp[y0*PW + x0]) + w01*__ldg(&mp[y0*PW + x1])
                        + w10*__ldg(&mp[y1*PW + x0]) + w11*__ldg(&mp[y1*PW + x1]);
                l[c] = uw*__ldg(&g_unary[((b*NC + c)*HH + y)*WW + xc]) + m;
            }
        }
        float mx = l[0];
#pragma unroll
        for (int c = 1; c < NC; c++) mx = fmaxf(mx, l[c]);
        float s = 0.f;
#pragma unroll
        for (int c = 0; c < NC; c++) { l[c] = __expf(l[c] - mx); s += l[c]; }
        float inv = 1.f / s;
#pragma unroll
        for (int c = 0; c < NC; c++) acc[c] += l[c]*inv;
    }
    // sum over groups of 4 lanes (4 input cols -> 1 pooled col)
#pragma unroll
    for (int c = 0; c < NC; c++) {
        float v = acc[c];
        v += __shfl_down_sync(0xffffffffu, v, 1);
        v += __shfl_down_sync(0xffffffffu, v, 2);
        acc[c] = v;
    }
    if ((tid & 3) == 0) {
        int pc = tile*32 + (tid >> 2);
#pragma unroll
        for (int c = 0; c < NC; c++)
            g_Qb[((b*NC + c)*PH + pr)*PW + pc] = acc[c]*(1.f/16.f);
    }
}

// -------- PAC message: msg[b,c,p] = sum_k wkern[b,k,p] * Qb[b,c,p+off(k)] (zero pad) --------
// block = 128 threads = pooled tile 32x4; channels processed 7 at a time via smem tiles
#define CHB 7
__global__ __launch_bounds__(128) void k_pac()
{
    __shared__ float sQ[CHB][14][42];      // rows: tile 4 + halo 10; cols: 32 + 10
    int b   = blockIdx.z;
    int ty0 = blockIdx.y * 4;              // pooled row origin
    int tx0 = blockIdx.x * 32;             // pooled col origin
    int tid = threadIdx.x;
    int tx  = tid & 31, ty = tid >> 5;
    int ph_ = ty0 + ty, pw_ = tx0 + tx;

    const float* wptr = &g_wkern[(b*K2)*PPLANE + ph_*PW + pw_];

    for (int cb = 0; cb < NC; cb += CHB) {
        __syncthreads();                   // protect smem reuse across passes
        for (int i = tid; i < CHB*14*42; i += 128) {
            int c   = i / (14*42);
            int r   = (i / 42) % 14;
            int col = i % 42;
            int gy = ty0 + r - 5, gx = tx0 + col - 5;
            float v = 0.f;
            if (gy >= 0 && gy < PH && gx >= 0 && gx < PW)
                v = __ldg(&g_Qb[((b*NC + cb + c)*PH + gy)*PW + gx]);
            sQ[c][r][col] = v;
        }
        __syncthreads();

        float acc[CHB];
#pragma unroll
        for (int c = 0; c < CHB; c++) acc[c] = 0.f;

        for (int ky = 0; ky < KS; ky++) {
#pragma unroll
            for (int kx = 0; kx < KS; kx++) {
                float wv = __ldg(wptr + (ky*KS + kx)*PPLANE);
                const float* s = &sQ[0][ty + ky][tx + kx];
#pragma unroll
                for (int c = 0; c < CHB; c++)
                    acc[c] += wv * s[c*(14*42)];
            }
        }
#pragma unroll
        for (int c = 0; c < CHB; c++)
            g_msg[((b*NC + cb + c)*PH + ph_)*PW + pw_] = acc[c];
    }
}

// -------- final: out = uw*unary + up4(msg), written to d_out --------
__global__ __launch_bounds__(256) void k_final(const float* __restrict__ uw_p,
                                               float* __restrict__ out)
{
    int i = blockIdx.x*256 + threadIdx.x;
    if (i >= BATCH*NC*HH*WW) return;
    int x  = i & (WW - 1);
    int y  = (i >> 9) & (HH - 1);
    int bc = i >> 18;                      // b*21 + c
    float uw = __ldg(uw_p);

    float srcY = (y + 0.5f)*0.25f - 0.5f;
    srcY = fminf(fmaxf(srcY, 0.f), 127.f);
    int   y0 = (int)floorf(srcY);
    int   y1 = min(y0 + 1, 127);
    float wy = srcY - (float)y0;

    float srcX = (x + 0.5f)*0.25f - 0.5f;
    srcX = fminf(fmaxf(srcX, 0.f), 127.f);
    int   x0 = (int)floorf(srcX);
    int   x1 = min(x0 + 1, 127);
    float wx = srcX - (float)x0;

    const float* mp = &g_msg[bc*PPLANE];
    float m = (1.f - wy)*((1.f - wx)*__ldg(&mp[y0*PW + x0]) + wx*__ldg(&mp[y0*PW + x1]))
            +        wy *((1.f - wx)*__ldg(&mp[y1*PW + x0]) + wx*__ldg(&mp[y1*PW + x1]));
    out[i] = uw*__ldg(&g_unary[i]) + m;
}

extern "C" void kernel_launch(void* const* d_in, const int* in_sizes, int n_in,
                              void* d_out, int out_size)
{
    const float* x    = (const float*)d_in[0];
    const float* w    = (const float*)d_in[1];
    const float* bias = (const float*)d_in[2];
    const float* uw   = (const float*)d_in[3];
    const float* pwts = (const float*)d_in[4];
    float* out = (float*)d_out;

    (void)in_sizes; (void)n_in; (void)out_size;

    // backbone + edge features + combined pairwise kernel (once)
    k_unary  <<<(BATCH*HH*WW + 255)/256, 256>>>(x, w, bias);
    k_poolrgb<<<(BATCH*3*PPLANE + 255)/256, 256>>>(x);
    k_wkern  <<<(BATCH*PPLANE + 127)/128, 128>>>(pwts);

    dim3 gSoft(4, PH, BATCH);
    dim3 gPac (PW/32, PH/4, BATCH);

    // step 0: Qb = pool(softmax(unary))
    k_softpool<<<gSoft, 128>>>(uw, 0);
    // 5 mean-field steps; intermediate logQ never materialized
    for (int t = 0; t < 5; t++) {
        k_pac<<<gPac, 128>>>();
        if (t < 4) k_softpool<<<gSoft, 128>>>(uw, 1);
        else       k_final<<<(BATCH*NC*HH*WW + 255)/256, 256>>>(uw, out);
    }
}